// round 14
// baseline (speedup 1.0000x reference)
#include <cuda_runtime.h>
#include <cuda_bf16.h>
#include <cstdint>

#define CC 256
#define NN 4096
#define BB 8

// ---------------- device globals (no runtime allocs allowed) ----------------
static __device__ __nv_bfloat16 g_Ah[CC * CC];      // A hi  [d][c]
static __device__ __nv_bfloat16 g_Al[CC * CC];      // A lo
static __device__ __nv_bfloat16 g_Xt_hi[(size_t)BB * NN * CC];  // X^T hi [b][n][c]
static __device__ __nv_bfloat16 g_Xt_lo[(size_t)BB * NN * CC];
static __device__ __nv_bfloat16 g_Zt_hi[(size_t)BB * NN * CC];  // Z^T hi [b][n][d]
static __device__ __nv_bfloat16 g_Zt_lo[(size_t)BB * NN * CC];
// split-softmax partials: [b*32+nt][mq][row]
static __device__ float g_pm[(size_t)BB * 32 * 4 * 128];
static __device__ float g_ps[(size_t)BB * 32 * 4 * 128];
static __device__ float g_dlog[(size_t)BB * 32 * 128];

// ---------------- helpers ----------------
__device__ __forceinline__ float fexp2(float x) {
    float y;
    asm("ex2.approx.ftz.f32 %0, %1;" : "=f"(y) : "f"(x));
    return y;
}
__device__ __forceinline__ uint32_t smem_u32(const void* p) {
    uint32_t a;
    asm("{ .reg .u64 t; cvta.to.shared.u64 t, %1; cvt.u32.u64 %0, t; }" : "=r"(a) : "l"(p));
    return a;
}
#define SWZ(o) ((o) ^ (((o) >> 3) & 0x70))

#define CP16(dst, src) \
    asm volatile("cp.async.cg.shared.global [%0], [%1], 16;" :: "r"(dst), "l"(src) : "memory")
#define CP_COMMIT() asm volatile("cp.async.commit_group;" ::: "memory")
#define CP_WAIT0()  asm volatile("cp.async.wait_group 0;" ::: "memory")

// mbarrier ops
#define MBAR_INIT(a, n) \
    asm volatile("mbarrier.init.shared.b64 [%0], %1;" :: "r"(a), "r"(n) : "memory")
#define MBAR_ARRIVE(a) \
    asm volatile("mbarrier.arrive.shared.b64 _, [%0];" :: "r"(a) : "memory")
#define CP_MBAR_ARRIVE(a) \
    asm volatile("cp.async.mbarrier.arrive.noinc.shared.b64 [%0];" :: "r"(a) : "memory")
#define MBAR_TRY(done, a, ph) \
    asm volatile("{\n\t.reg .pred p;\n\t"                                       \
        "mbarrier.try_wait.parity.acquire.cta.shared::cta.b64 p, [%1], %2;\n\t" \
        "selp.b32 %0, 1, 0, p;\n\t}" : "=r"(done) : "r"(a), "r"(ph) : "memory")
#define MBAR_LOOP(a, ph) \
    asm volatile("{\n\t.reg .pred P1;\n\tWL_%=:\n\t"                            \
        "mbarrier.try_wait.parity.acquire.cta.shared::cta.b64 P1, [%0], %1, 0x989680;\n\t" \
        "@P1 bra.uni WD_%=;\n\tbra.uni WL_%=;\n\tWD_%=:\n\t}"                   \
        :: "r"(a), "r"(ph) : "memory")
#define MBAR_WAIT(a, ph) do {                                                   \
    uint32_t _m = (a), _p = (ph), _d;                                           \
    MBAR_TRY(_d, _m, _p);                                                       \
    if (!_d) MBAR_LOOP(_m, _p);                                                 \
} while (0)

__device__ __forceinline__ void ldsm4(uint32_t* r, uint32_t a) {
    asm volatile("ldmatrix.sync.aligned.m8n8.x4.shared.b16 {%0,%1,%2,%3}, [%4];"
        : "=r"(r[0]), "=r"(r[1]), "=r"(r[2]), "=r"(r[3]) : "r"(a));
}
__device__ __forceinline__ void mma16816(float* d, const uint32_t* a, const uint32_t* b) {
    asm volatile("mma.sync.aligned.m16n8k16.row.col.f32.bf16.bf16.f32 "
        "{%0,%1,%2,%3}, {%4,%5,%6,%7}, {%8,%9}, {%0,%1,%2,%3};"
        : "+f"(d[0]), "+f"(d[1]), "+f"(d[2]), "+f"(d[3])
        : "r"(a[0]), "r"(a[1]), "r"(a[2]), "r"(a[3]), "r"(b[0]), "r"(b[1]));
}
__device__ __forceinline__ uint32_t pack_bf16x2(__nv_bfloat16 a, __nv_bfloat16 b) {
    return (uint32_t)__bfloat16_as_ushort(a) | ((uint32_t)__bfloat16_as_ushort(b) << 16);
}

// ---------------------------------------------------------------------------
// k_prepA (R14: smem-tiled): A[d][c] = log2e * sum_e Wq[e][c] * Wk[e][d]
// grid (8,8) CTAs of 32x32 outputs; 256 threads; K chunked by 64.
// ---------------------------------------------------------------------------
__global__ __launch_bounds__(256) void k_prepA(const float* __restrict__ Wq,
                                               const float* __restrict__ Wk) {
    __shared__ float sq[64][33];
    __shared__ float sk[64][33];
    const float LOG2E = 1.4426950408889634f;
    const int tid = threadIdx.x;
    const int tx = tid & 31, tg = tid >> 5;       // tx: c_local, tg: d_group
    const int c0 = blockIdx.x * 32, d0 = blockIdx.y * 32;

    float s[4] = {0.f, 0.f, 0.f, 0.f};
#pragma unroll 1
    for (int kc = 0; kc < CC; kc += 64) {
        __syncthreads();
#pragma unroll
        for (int t = 0; t < 8; t++) {
            int o = tid + t * 256;
            int e = o >> 5, cl = o & 31;
            sq[e][cl] = Wq[(kc + e) * CC + c0 + cl];
            sk[e][cl] = Wk[(kc + e) * CC + d0 + cl];
        }
        __syncthreads();
#pragma unroll 8
        for (int e = 0; e < 64; e++) {
            float q = sq[e][tx];
#pragma unroll
            for (int i = 0; i < 4; i++)
                s[i] = fmaf(q, sk[e][tg + 8 * i], s[i]);
        }
    }
#pragma unroll
    for (int i = 0; i < 4; i++) {
        float v = s[i] * LOG2E;
        __nv_bfloat16 h = __float2bfloat16(v);
        int d = d0 + tg + 8 * i;
        g_Ah[d * CC + c0 + tx] = h;
        g_Al[d * CC + c0 + tx] = __float2bfloat16(v - __bfloat162float(h));
    }
}

// ---------------------------------------------------------------------------
// Transpose + bf16 hi/lo split: X[b][c][n] -> Xt_hi/lo[b][n][c]
// ---------------------------------------------------------------------------
__global__ __launch_bounds__(256) void k_prep(const float* __restrict__ X) {
    __shared__ float s[32][33];
    const int b = blockIdx.z, c0 = blockIdx.y * 32, n0 = blockIdx.x * 32;
    const int tx = threadIdx.x, ty = threadIdx.y;
    const float* Xb = X + (size_t)b * CC * NN;
#pragma unroll
    for (int i = 0; i < 4; i++)
        s[ty + 8 * i][tx] = Xb[(size_t)(c0 + ty + 8 * i) * NN + n0 + tx];
    __syncthreads();
    const size_t base = (size_t)b * NN * CC;
#pragma unroll
    for (int i = 0; i < 4; i++) {
        int n = n0 + ty + 8 * i;
        float v = s[tx][ty + 8 * i];
        __nv_bfloat16 h = __float2bfloat16(v);
        g_Xt_hi[base + (size_t)n * CC + c0 + tx] = h;
        g_Xt_lo[base + (size_t)n * CC + c0 + tx] =
            __float2bfloat16(v - __bfloat162float(h));
    }
}

// ---------------------------------------------------------------------------
// k_Zt (R14: 512-thread 4x4 port of the k_part microkernel):
// Zt[n][d] = sum_c Xt[n][c] * A[d][c]   (3-term bf16 split, mma.sync)
// grid (32 nt, 2 dt, 8 b); CTA tile 128(n) x 128(d); K = 256 in 4 chunks
// of 64, double-buffered (2 x 64KB smem).
// ---------------------------------------------------------------------------
__global__ __launch_bounds__(512, 1) void k_Zt() {
    extern __shared__ char smem[];
    const uint32_t sb = smem_u32(smem);
    const int tid = threadIdx.x;
    const int wid = tid >> 5, lane = tid & 31;
    const int wr = wid >> 2, wc = wid & 3;
    const int n0 = blockIdx.x << 7;
    const int d0 = blockIdx.y << 7;
    const int b = blockIdx.z;
    const size_t bbase = (size_t)b * NN * CC;
    const char* Xsrc[2] = {(const char*)(g_Xt_hi + bbase), (const char*)(g_Xt_lo + bbase)};
    const char* Asrc[2] = {(const char*)g_Ah, (const char*)g_Al};

    const int aColX = (lane >> 4) << 4;
    const int bRowOff = (lane & 7) + ((lane >> 4) & 1) * 8;
    const int bColX = ((lane >> 3) & 1) << 4;

    float acc[2][4][4];
#pragma unroll
    for (int i = 0; i < 2; i++)
#pragma unroll
        for (int j = 0; j < 4; j++)
#pragma unroll
            for (int k = 0; k < 4; k++) acc[i][j][k] = 0.f;

    // prologue: chunk 0 into buffer 0
#pragma unroll
    for (int t = 0; t < 8; t++) {
        int o = tid + t * 512;
        int role = o >> 10, r = (o >> 3) & 127, j = o & 7;
        const char* src = (role < 2)
            ? Xsrc[role] + ((size_t)(n0 + r) * CC) * 2 + j * 16
            : Asrc[role - 2] + ((size_t)(d0 + r) * CC) * 2 + j * 16;
        uint32_t dst = sb + (uint32_t)role * 16384u + SWZ((uint32_t)(r * 128 + j * 16));
        CP16(dst, src);
    }
    CP_COMMIT();

#pragma unroll 1
    for (int cc = 0; cc < 4; cc++) {
        const int buf = cc & 1;
        CP_WAIT0();
        __syncthreads();
        if (cc < 3) {
            const int cn = cc + 1, bn = buf ^ 1;
#pragma unroll
            for (int t = 0; t < 8; t++) {
                int o = tid + t * 512;
                int role = o >> 10, r = (o >> 3) & 127, j = o & 7;
                const char* src = (role < 2)
                    ? Xsrc[role] + ((size_t)(n0 + r) * CC + cn * 64) * 2 + j * 16
                    : Asrc[role - 2] + ((size_t)(d0 + r) * CC + cn * 64) * 2 + j * 16;
                uint32_t dst = sb + (uint32_t)bn * 65536u + (uint32_t)role * 16384u +
                               SWZ((uint32_t)(r * 128 + j * 16));
                CP16(dst, src);
            }
        }
        CP_COMMIT();

        const uint32_t xh = sb + (uint32_t)buf * 65536u;
        const uint32_t xl = xh + 16384u;
        const uint32_t ah = xh + 32768u;
        const uint32_t al = xh + 49152u;
#pragma unroll
        for (int ks = 0; ks < 4; ks++) {
            const int cb = ks * 32;
            uint32_t Ah[2][4], Al[2][4], Bh[2][4], Bl[2][4];
#pragma unroll
            for (int rb = 0; rb < 2; rb++) {
                int row = wr * 32 + rb * 16 + (lane & 15);
                uint32_t off = (uint32_t)(row * 128) +
                               (uint32_t)((cb + aColX) ^ ((row * 16) & 0x70));
                ldsm4(Ah[rb], xh + off);
                ldsm4(Al[rb], xl + off);
            }
#pragma unroll
            for (int cs = 0; cs < 2; cs++) {
                int row = wc * 32 + cs * 16 + bRowOff;
                uint32_t off = (uint32_t)(row * 128) +
                               (uint32_t)((cb + bColX) ^ ((row * 16) & 0x70));
                ldsm4(Bh[cs], ah + off);
                ldsm4(Bl[cs], al + off);
            }
#pragma unroll
            for (int rb = 0; rb < 2; rb++)
#pragma unroll
                for (int cs = 0; cs < 2; cs++) {
                    mma16816(acc[rb][cs * 2],     Ah[rb], Bh[cs]);
                    mma16816(acc[rb][cs * 2 + 1], Ah[rb], Bh[cs] + 2);
                }
#pragma unroll
            for (int rb = 0; rb < 2; rb++)
#pragma unroll
                for (int cs = 0; cs < 2; cs++) {
                    mma16816(acc[rb][cs * 2],     Ah[rb], Bl[cs]);
                    mma16816(acc[rb][cs * 2 + 1], Ah[rb], Bl[cs] + 2);
                }
#pragma unroll
            for (int rb = 0; rb < 2; rb++)
#pragma unroll
                for (int cs = 0; cs < 2; cs++) {
                    mma16816(acc[rb][cs * 2],     Al[rb], Bh[cs]);
                    mma16816(acc[rb][cs * 2 + 1], Al[rb], Bh[cs] + 2);
                }
        }
    }

    // store Zt hi/lo.  acc[rb][j][k]: n = n0+wr*32+rb*16+(k>>1)*8+(lane>>2),
    // d = d0+wc*32+j*8+(lane&3)*2+(k&1).  Pack (k&1)=0,1 as bf16x2.
    char* Zh = (char*)(g_Zt_hi + bbase);
    char* Zl = (char*)(g_Zt_lo + bbase);
#pragma unroll
    for (int rb = 0; rb < 2; rb++)
#pragma unroll
        for (int h = 0; h < 2; h++) {
            int n = n0 + wr * 32 + rb * 16 + h * 8 + (lane >> 2);
#pragma unroll
            for (int j = 0; j < 4; j++) {
                float v0 = acc[rb][j][2 * h], v1 = acc[rb][j][2 * h + 1];
                __nv_bfloat16 h0 = __float2bfloat16(v0);
                __nv_bfloat16 h1 = __float2bfloat16(v1);
                __nv_bfloat16 l0 = __float2bfloat16(v0 - __bfloat162float(h0));
                __nv_bfloat16 l1 = __float2bfloat16(v1 - __bfloat162float(h1));
                size_t off = ((size_t)n * CC + d0 + wc * 32 + j * 8 + 2 * (lane & 3)) * 2;
                *(uint32_t*)(Zh + off) = pack_bf16x2(h0, h1);
                *(uint32_t*)(Zl + off) = pack_bf16x2(l0, l1);
            }
        }
}

// ---------------------------------------------------------------------------
// k_part: UNCHANGED from R13 (707us best): grid B*32*4, 512 threads, 4x4
// warp grid, Z persistent, X triple-buffered, mbarrier producer/consumer,
// split try/produce/loop full-wait, half-phase ks interleave.
// ---------------------------------------------------------------------------
#define SM_ZS 0u
#define SM_XS 131072u
#define SM_MBAR 229376u
#define SM_TOTAL (229376 + 64)

__global__ __launch_bounds__(512, 1) void k_part() {
    extern __shared__ char smem[];
    const uint32_t sb = smem_u32(smem);
    const int tid = threadIdx.x;
    const int wid = tid >> 5, lane = tid & 31;
    const int wr = wid >> 2, wc = wid & 3;
    const int g = lane >> 2;
    const int bx = blockIdx.x;
    const int b = bx >> 7;
    const int nt = (bx >> 2) & 31;
    const int mq = bx & 3;
    const int n0 = nt << 7;
    const size_t bbase = (size_t)b * NN * CC;
    const char* Zsrc[2] = {(const char*)(g_Zt_hi + bbase), (const char*)(g_Zt_lo + bbase)};
    const char* Xsrc[2] = {(const char*)(g_Xt_hi + bbase), (const char*)(g_Xt_lo + bbase)};

    const uint32_t mb_full = sb + SM_MBAR;        // full[k] = +8k
    const uint32_t mb_free = sb + SM_MBAR + 24;   // free[k] = +24+8k

    const int aColX = (lane >> 4) << 4;
    const int bRowOff = (lane & 7) + ((lane >> 4) & 1) * 8;
    const int bColX = ((lane >> 3) & 1) << 4;

    if (tid == 0) {
#pragma unroll
        for (int k = 0; k < 3; k++) {
            MBAR_INIT(mb_full + k * 8, 512);
            MBAR_INIT(mb_free + k * 8, 512);
        }
    }
    __syncthreads();

    MBAR_ARRIVE(mb_free + 0);
    MBAR_ARRIVE(mb_free + 8);
    MBAR_ARRIVE(mb_free + 16);

    // Z (8 tiles, SW128)
#pragma unroll
    for (int t = 0; t < 16; t++) {
        int o = tid + t * 512;
        int ch = o >> 11, hs = (o >> 10) & 1, r = (o >> 3) & 127, j = o & 7;
        const char* src = Zsrc[hs] + ((size_t)(n0 + r) * CC + ch * 64) * 2 + j * 16;
        uint32_t dst = sb + SM_ZS + (uint32_t)(ch * 2 + hs) * 16384u +
                       SWZ((uint32_t)(r * 128 + j * 16));
        CP16(dst, src);
    }
    {
        const int m00 = (mq * 8) << 7;
#pragma unroll
        for (int t = 0; t < 4; t++) {
            int o = tid + t * 512;
            int hs = o >> 10, r = (o >> 3) & 127, j = o & 7;
            const char* src = Xsrc[hs] + ((size_t)(m00 + r) * CC) * 2 + j * 16;
            uint32_t dst = sb + SM_XS + (uint32_t)hs * 16384u +
                           SWZ((uint32_t)(r * 128 + j * 16));
            CP16(dst, src);
        }
        CP_MBAR_ARRIVE(mb_full + 0);
#pragma unroll
        for (int t = 0; t < 4; t++) {
            int o = tid + t * 512;
            int hs = o >> 10, r = (o >> 3) & 127, j = o & 7;
            const char* src = Xsrc[hs] + ((size_t)(m00 + r) * CC + 64) * 2 + j * 16;
            uint32_t dst = sb + SM_XS + 32768u + (uint32_t)hs * 16384u +
                           SWZ((uint32_t)(r * 128 + j * 16));
            CP16(dst, src);
        }
        CP_MBAR_ARRIVE(mb_full + 8);
    }

    float acc[2][4][4];
#pragma unroll
    for (int i = 0; i < 2; i++)
#pragma unroll
        for (int j = 0; j < 4; j++)
#pragma unroll
            for (int k = 0; k < 4; k++) acc[i][j][k] = 0.f;
    float mrun[2][2], rsum[2][2];
#pragma unroll
    for (int i = 0; i < 2; i++)
#pragma unroll
        for (int j = 0; j < 2; j++) { mrun[i][j] = -3.0e38f; rsum[i][j] = 0.f; }

#pragma unroll 1
    for (int G = 0; G < 32; G++) {
        const int cc = G & 3, mtl = G >> 2;
        const int buf = G % 3;

        uint32_t full_done;
        MBAR_TRY(full_done, mb_full + buf * 8, (G / 3) & 1);

        const int Gn = G + 2;
        if (Gn < 32) {
            const int k2 = Gn % 3;
            MBAR_WAIT(mb_free + k2 * 8, (Gn / 3) & 1);
            const int ccn = Gn & 3, m0n = (mq * 8 + (Gn >> 2)) << 7;
#pragma unroll
            for (int t = 0; t < 4; t++) {
                int o = tid + t * 512;
                int hs = o >> 10, r = (o >> 3) & 127, j = o & 7;
                const char* src = Xsrc[hs] + ((size_t)(m0n + r) * CC + ccn * 64) * 2 + j * 16;
                uint32_t dst = sb + SM_XS + (uint32_t)k2 * 32768u +
                               (uint32_t)hs * 16384u + SWZ((uint32_t)(r * 128 + j * 16));
                CP16(dst, src);
            }
            CP_MBAR_ARRIVE(mb_full + k2 * 8);
        }

        if (!full_done) MBAR_LOOP(mb_full + buf * 8, (G / 3) & 1);

        const uint32_t zh = sb + SM_ZS + (uint32_t)(cc * 2) * 16384u;
        const uint32_t zl = zh + 16384u;
        const uint32_t xh = sb + SM_XS + (uint32_t)buf * 32768u;
        const uint32_t xl = xh + 16384u;
#pragma unroll
        for (int ks = 0; ks < 4; ks++) {
            const int cb = ks * 32;
            uint32_t Ah[2][4], Al[2][4], Bh[2][4], Bl[2][4];
#pragma unroll
            for (int rb = 0; rb < 2; rb++) {
                int row = wr * 32 + rb * 16 + (lane & 15);
                uint32_t off = (uint32_t)(row * 128) +
                               (uint32_t)((cb + aColX) ^ ((row * 16) & 0x70));
                ldsm4(Ah[rb], zh + off);
                ldsm4(Al[rb], zl + off);
            }
            {
                int row = wc * 32 + 0 * 16 + bRowOff;
                uint32_t off = (uint32_t)(row * 128) +
                               (uint32_t)((cb + bColX) ^ ((row * 16) & 0x70));
                ldsm4(Bh[0], xh + off);
                ldsm4(Bl[0], xl + off);
            }
#pragma unroll
            for (int rb = 0; rb < 2; rb++) {
                mma16816(acc[rb][0], Ah[rb], Bh[0]);
                mma16816(acc[rb][1], Ah[rb], Bh[0] + 2);
            }
#pragma unroll
            for (int rb = 0; rb < 2; rb++) {
                mma16816(acc[rb][0], Ah[rb], Bl[0]);
                mma16816(acc[rb][1], Ah[rb], Bl[0] + 2);
            }
            {
                int row = wc * 32 + 1 * 16 + bRowOff;
                uint32_t off = (uint32_t)(row * 128) +
                               (uint32_t)((cb + bColX) ^ ((row * 16) & 0x70));
                ldsm4(Bh[1], xh + off);
                ldsm4(Bl[1], xl + off);
            }
#pragma unroll
            for (int rb = 0; rb < 2; rb++) {
                mma16816(acc[rb][0], Al[rb], Bh[0]);
                mma16816(acc[rb][1], Al[rb], Bh[0] + 2);
            }
#pragma unroll
            for (int rb = 0; rb < 2; rb++) {
                mma16816(acc[rb][2], Ah[rb], Bh[1]);
                mma16816(acc[rb][3], Ah[rb], Bh[1] + 2);
            }
#pragma unroll
            for (int rb = 0; rb < 2; rb++) {
                mma16816(acc[rb][2], Ah[rb], Bl[1]);
                mma16816(acc[rb][3], Ah[rb], Bl[1] + 2);
            }
#pragma unroll
            for (int rb = 0; rb < 2; rb++) {
                mma16816(acc[rb][2], Al[rb], Bh[1]);
                mma16816(acc[rb][3], Al[rb], Bh[1] + 2);
            }
        }

        if (cc != 3) {
            MBAR_ARRIVE(mb_free + buf * 8);
        } else {
            __syncthreads();
            float* pmax = (float*)(smem + SM_XS + (uint32_t)buf * 32768u);
            float* psum = pmax + 512;

#pragma unroll
            for (int rb = 0; rb < 2; rb++)
#pragma unroll
                for (int rh = 0; rh < 2; rh++) {
                    float tm = -3.0e38f;
#pragma unroll
                    for (int j = 0; j < 4; j++)
                        tm = fmaxf(tm, fmaxf(acc[rb][j][2 * rh], acc[rb][j][2 * rh + 1]));
                    tm = fmaxf(tm, __shfl_xor_sync(0xffffffffu, tm, 1));
                    tm = fmaxf(tm, __shfl_xor_sync(0xffffffffu, tm, 2));
                    float ps = 0.f;
#pragma unroll
                    for (int j = 0; j < 4; j++) {
                        ps += fexp2(acc[rb][j][2 * rh] - tm);
                        ps += fexp2(acc[rb][j][2 * rh + 1] - tm);
                    }
                    ps += __shfl_xor_sync(0xffffffffu, ps, 1);
                    ps += __shfl_xor_sync(0xffffffffu, ps, 2);
                    if ((lane & 3) == 0) {
                        int rl = wr * 32 + rb * 16 + rh * 8 + g;
                        pmax[wc * 128 + rl] = tm;
                        psum[wc * 128 + rl] = ps;
                    }
                }
            if (mq == (nt >> 3) && mtl == (nt & 7) && wr == wc) {
#pragma unroll
                for (int rb = 0; rb < 2; rb++)
#pragma unroll
                    for (int rh = 0; rh < 2; rh++) {
                        int cl = rb * 16 + rh * 8 + g;
                        if ((lane & 3) == ((cl & 7) >> 1))
                            g_dlog[(size_t)(b * 32 + nt) * 128 + wr * 32 + cl] =
                                acc[rb][rb * 2 + rh][2 * rh + (cl & 1)];
                    }
            }
            __syncthreads();
#pragma unroll
            for (int rb = 0; rb < 2; rb++)
#pragma unroll
                for (int rh = 0; rh < 2; rh++) {
                    int rl = wr * 32 + rb * 16 + rh * 8 + g;
                    float mn = mrun[rb][rh];
#pragma unroll
                    for (int j = 0; j < 4; j++) mn = fmaxf(mn, pmax[j * 128 + rl]);
                    float rs = rsum[rb][rh] * fexp2(mrun[rb][rh] - mn);
#pragma unroll
                    for (int j = 0; j < 4; j++)
                        rs += fexp2(pmax[j * 128 + rl] - mn) * psum[j * 128 + rl];
                    mrun[rb][rh] = mn;
                    rsum[rb][rh] = rs;
                }
#pragma unroll
            for (int i = 0; i < 2; i++)
#pragma unroll
                for (int j = 0; j < 4; j++)
#pragma unroll
                    for (int k = 0; k < 4; k++) acc[i][j][k] = 0.f;
            MBAR_ARRIVE(mb_free + buf * 8);
        }
    }

    if (wc == 0 && (lane & 3) == 0) {
#pragma unroll
        for (int rb = 0; rb < 2; rb++)
#pragma unroll
            for (int rh = 0; rh < 2; rh++) {
                int rl = wr * 32 + rb * 16 + rh * 8 + g;
                g_pm[(size_t)bx * 128 + rl] = mrun[rb][rh];
                g_ps[(size_t)bx * 128 + rl] = rsum[rb][rh];
            }
    }
}

// ---------------------------------------------------------------------------
// k_final: combine 4 partials -> diag; out[b][c][n0..] = X * diag
// ---------------------------------------------------------------------------
__global__ __launch_bounds__(512) void k_final(const float* __restrict__ X,
                                               float* __restrict__ out) {
    __shared__ float sdiag[128];
    const int bx = blockIdx.x;
    const int b = bx >> 5, nt = bx & 31;
    const int n0 = nt << 7;
    const int tid = threadIdx.x;

    if (tid < 128) {
        float pm[4];
        float M = -3.0e38f;
#pragma unroll
        for (int q = 0; q < 4; q++) {
            pm[q] = g_pm[((size_t)bx * 4 + q) * 128 + tid];
            M = fmaxf(M, pm[q]);
        }
        float S = 0.f;
#pragma unroll
        for (int q = 0; q < 4; q++)
            S += g_ps[((size_t)bx * 4 + q) * 128 + tid] * fexp2(pm[q] - M);
        sdiag[tid] = fexp2(g_dlog[(size_t)bx * 128 + tid] - M) / S *
                     (1.0f / (1.0f + 1e-8f));
    }
    __syncthreads();

    const float* Xb = X + (size_t)b * CC * NN;
    float* Ob = out + (size_t)b * CC * NN;
#pragma unroll 4
    for (int t = 0; t < 16; t++) {
        int f = tid + t * 512;
        int row = f >> 5;
        int c4 = (f & 31) << 2;
        float4 v = *(const float4*)&Xb[(size_t)row * NN + n0 + c4];
        float4 dv = *(const float4*)&sdiag[c4];
        v.x *= dv.x; v.y *= dv.y; v.z *= dv.z; v.w *= dv.w;
        *(float4*)&Ob[(size_t)row * NN + n0 + c4] = v;
    }
}

// ---------------------------------------------------------------------------
extern "C" void kernel_launch(void* const* d_in, const int* in_sizes, int n_in,
                              void* d_out, int out_size) {
    const float* X  = (const float*)d_in[0];
    const float* Wq = (const float*)d_in[1];
    const float* Wk = (const float*)d_in[2];
    float* out = (float*)d_out;

    cudaFuncSetAttribute(k_Zt, cudaFuncAttributeMaxDynamicSharedMemorySize, 131072);
    cudaFuncSetAttribute(k_part, cudaFuncAttributeMaxDynamicSharedMemorySize, SM_TOTAL);

    k_prepA<<<dim3(8, 8), 256>>>(Wq, Wk);
    k_prep<<<dim3(NN / 32, CC / 32, BB), dim3(32, 8)>>>(X);
    k_Zt<<<dim3(32, 2, BB), 512, 131072>>>();
    k_part<<<BB * 32 * 4, 512, SM_TOTAL>>>();
    k_final<<<BB * 32, 512>>>(X, out);
}